// round 1
// baseline (speedup 1.0000x reference)
#include <cuda_runtime.h>
#include <cuda_bf16.h>
#include <cstdint>

// Problem: y = Re(FFT_2048(x_row)); out = LayerNorm(y) * gamma + beta
// B*N = 16384 rows, C = 2048.
//
// Algorithm per row (one CTA of 256 threads):
//   1. Pack real row as 1024 complex: z[n] = x[2n] + i x[2n+1]  (free: reinterpret as float2)
//   2. 1024-pt complex FFT, radix-4 Stockham autosort, 5 stages, ping-pong in smem.
//      Twiddles from a precomputed __device__ table of 2048th roots (L1-resident).
//   3. Real-FFT unpack: ReX[k] = ((a+c) + cos(b+d) - sin(a-c))/2 with Z[k]=(a,b),
//      Z[1024-k]=(c,d), theta = 2*pi*k/2048; mirror ReX[2048-k] = ReX[k].
//   4. LayerNorm reduction (sum, sumsq) + normalize + gamma/beta, vectorized stores.

#define THREADS 256
#define H 1024          // complex FFT size
#define C 2048          // row length

__device__ float2 g_tw[2048];   // g_tw[t] = exp(-i * 2*pi * t / 2048) = (cos, -sin)

__global__ void fill_tw_kernel() {
    int t = blockIdx.x * blockDim.x + threadIdx.x;
    if (t < 2048) {
        float s, c;
        sincospif(-(float)t / 1024.0f, &s, &c);   // angle = -pi*t/1024 = -2*pi*t/2048
        g_tw[t] = make_float2(c, s);
    }
}

__device__ __forceinline__ float2 cmul(float2 a, float2 b) {
    return make_float2(fmaf(a.x, b.x, -a.y * b.y), fmaf(a.x, b.y, a.y * b.x));
}

// Forward radix-4 DFT (exp(-i) convention):
// out0 = v0+v1+v2+v3 ; out1 = v0 - i v1 - v2 + i v3
// out2 = v0-v1+v2-v3 ; out3 = v0 + i v1 - v2 - i v3
__device__ __forceinline__ void bfly4(float2 v[4]) {
    float2 t0 = make_float2(v[0].x + v[2].x, v[0].y + v[2].y);
    float2 t1 = make_float2(v[0].x - v[2].x, v[0].y - v[2].y);
    float2 t2 = make_float2(v[1].x + v[3].x, v[1].y + v[3].y);
    float2 t3 = make_float2(v[1].x - v[3].x, v[1].y - v[3].y);
    v[0] = make_float2(t0.x + t2.x, t0.y + t2.y);
    v[2] = make_float2(t0.x - t2.x, t0.y - t2.y);
    v[1] = make_float2(t1.x + t3.y, t1.y - t3.x);   // t1 + (-i)*t3
    v[3] = make_float2(t1.x - t3.y, t1.y + t3.x);   // t1 + ( i)*t3
}

template <int NS, int LOG2NS>
__device__ __forceinline__ void stage(const float2* __restrict__ in,
                                      float2* __restrict__ out, int j) {
    float2 v[4];
#pragma unroll
    for (int r = 0; r < 4; r++) v[r] = in[j + r * 256];
    if (NS > 1) {
        int m = j & (NS - 1);
        const int step = 2048 / (NS * 4);
#pragma unroll
        for (int r = 1; r < 4; r++) {
            float2 w = __ldg(&g_tw[r * m * step]);
            v[r] = cmul(v[r], w);
        }
    }
    bfly4(v);
    int idxD = ((j >> LOG2NS) << (LOG2NS + 2)) + (j & (NS - 1));
#pragma unroll
    for (int r = 0; r < 4; r++) out[idxD + r * NS] = v[r];
}

__global__ void __launch_bounds__(THREADS, 8)
fourier_ln_kernel(const float* __restrict__ x,
                  const float* __restrict__ gamma,
                  const float* __restrict__ beta,
                  float* __restrict__ out) {
    __shared__ __align__(16) float2 bufA[H];
    __shared__ __align__(16) float2 bufB[H];
    __shared__ float red[18];

    const int j = threadIdx.x;
    const size_t row = blockIdx.x;
    const float2* xr = reinterpret_cast<const float2*>(x) + row * H;

    // ---- stage 1 (Ns=1): global -> registers -> bufA, no twiddle ----
    {
        float2 v[4];
#pragma unroll
        for (int r = 0; r < 4; r++) v[r] = xr[j + r * 256];
        bfly4(v);
        int idxD = j << 2;
#pragma unroll
        for (int r = 0; r < 4; r++) bufA[idxD + r] = v[r];
    }
    __syncthreads();
    stage<4, 2>(bufA, bufB, j);   __syncthreads();
    stage<16, 4>(bufB, bufA, j);  __syncthreads();
    stage<64, 6>(bufA, bufB, j);  __syncthreads();
    stage<256, 8>(bufB, bufA, j); __syncthreads();
    // Z (natural order) now in bufA.

    // ---- real-FFT unpack into sreal (reuse bufB: 2048 floats) ----
    float* sreal = reinterpret_cast<float*>(bufB);
#pragma unroll
    for (int r = 0; r < 4; r++) {
        int k = j + r * 256;                 // k in [0, 1024)
        float2 z  = bufA[k];
        float2 zc = bufA[(H - k) & (H - 1)];
        float2 w  = __ldg(&g_tw[k]);         // (cos th, -sin th), th = 2*pi*k/2048
        // ReX[k] = 0.5*((a+c) + cos*(b+d) - sin*(a-c))
        float re = 0.5f * ((z.x + zc.x) + fmaf(w.x, (z.y + zc.y), w.y * (z.x - zc.x)));
        sreal[k] = re;
        sreal[(C - k) & (C - 1)] = re;       // mirror (k=0 rewrites index 0, same value)
    }
    if (j == 0) {
        float2 z0 = bufA[0];
        sreal[H] = z0.x - z0.y;              // ReX[1024] = ReZ[0] - ImZ[0]
    }
    __syncthreads();

    // ---- LayerNorm reduction ----
    const float4* rv = reinterpret_cast<const float4*>(sreal);
    float4 p = rv[2 * j];
    float4 q = rv[2 * j + 1];
    float s  = p.x + p.y + p.z + p.w + q.x + q.y + q.z + q.w;
    float ss = fmaf(p.x, p.x, fmaf(p.y, p.y, fmaf(p.z, p.z, fmaf(p.w, p.w,
               fmaf(q.x, q.x, fmaf(q.y, q.y, fmaf(q.z, q.z, q.w * q.w)))))));
#pragma unroll
    for (int off = 16; off > 0; off >>= 1) {
        s  += __shfl_xor_sync(0xFFFFFFFFu, s, off);
        ss += __shfl_xor_sync(0xFFFFFFFFu, ss, off);
    }
    int lane = j & 31, wid = j >> 5;
    if (lane == 0) { red[wid] = s; red[8 + wid] = ss; }
    __syncthreads();
    if (j == 0) {
        float S = 0.f, SS = 0.f;
#pragma unroll
        for (int w = 0; w < 8; w++) { S += red[w]; SS += red[8 + w]; }
        float mu  = S * (1.0f / C);
        float var = SS * (1.0f / C) - mu * mu;
        red[16] = mu;
        red[17] = rsqrtf(var + 1e-5f);
    }
    __syncthreads();
    float mu = red[16], rstd = red[17];

    // ---- normalize + affine + store (this thread owns elements [8j, 8j+8)) ----
    const float4* g4 = reinterpret_cast<const float4*>(gamma);
    const float4* b4 = reinterpret_cast<const float4*>(beta);
    float4* o4 = reinterpret_cast<float4*>(out) + row * (C / 4);
    {
        int i0 = 2 * j, i1 = 2 * j + 1;
        float4 g0 = __ldg(&g4[i0]), b0 = __ldg(&b4[i0]);
        float4 g1 = __ldg(&g4[i1]), b1 = __ldg(&b4[i1]);
        float4 o0, o1;
        o0.x = fmaf((p.x - mu) * rstd, g0.x, b0.x);
        o0.y = fmaf((p.y - mu) * rstd, g0.y, b0.y);
        o0.z = fmaf((p.z - mu) * rstd, g0.z, b0.z);
        o0.w = fmaf((p.w - mu) * rstd, g0.w, b0.w);
        o1.x = fmaf((q.x - mu) * rstd, g1.x, b1.x);
        o1.y = fmaf((q.y - mu) * rstd, g1.y, b1.y);
        o1.z = fmaf((q.z - mu) * rstd, g1.z, b1.z);
        o1.w = fmaf((q.w - mu) * rstd, g1.w, b1.w);
        o4[i0] = o0;
        o4[i1] = o1;
    }
}

extern "C" void kernel_launch(void* const* d_in, const int* in_sizes, int n_in,
                              void* d_out, int out_size) {
    const float* x     = (const float*)d_in[0];
    const float* gamma = (const float*)d_in[1];
    const float* beta  = (const float*)d_in[2];
    float* out = (float*)d_out;

    int rows = in_sizes[0] / C;   // B*N = 16384

    fill_tw_kernel<<<8, 256>>>();
    fourier_ln_kernel<<<rows, THREADS>>>(x, gamma, beta, out);
}

// round 2
// speedup vs baseline: 2.5428x; 2.5428x over previous
#include <cuda_runtime.h>
#include <cuda_bf16.h>
#include <cstdint>

// y = Re(FFT_2048(x_row)); out = LayerNorm(y)*gamma + beta.  16384 rows, C=2048.
// One CTA (256 thr) per row. Pack as 1024-pt complex FFT (radix-4 Stockham,
// 5 stages). Padded smem addressing (per-buffer pad factor) -> conflict-free
// scatter writes. Final stage + unpack + LayerNorm register-resident.

#define THREADS 256
#define H 1024
#define C 2048
#define PI_F 3.14159265358979323846f
#define RS2 0.70710678118654752f

__device__ __forceinline__ float2 cmul(float2 a, float2 b) {
    return make_float2(fmaf(a.x, b.x, -a.y * b.y), fmaf(a.x, b.y, a.y * b.x));
}

// Forward radix-4 DFT (exp(-i) convention).
__device__ __forceinline__ void bfly4(float2 v[4]) {
    float2 t0 = make_float2(v[0].x + v[2].x, v[0].y + v[2].y);
    float2 t1 = make_float2(v[0].x - v[2].x, v[0].y - v[2].y);
    float2 t2 = make_float2(v[1].x + v[3].x, v[1].y + v[3].y);
    float2 t3 = make_float2(v[1].x - v[3].x, v[1].y - v[3].y);
    v[0] = make_float2(t0.x + t2.x, t0.y + t2.y);
    v[2] = make_float2(t0.x - t2.x, t0.y - t2.y);
    v[1] = make_float2(t1.x + t3.y, t1.y - t3.x);   // t1 + (-i)t3
    v[3] = make_float2(t1.x - t3.y, t1.y + t3.x);   // t1 + ( i)t3
}

template <int D>
__device__ __forceinline__ int pad(int i) { return i + ((i >> 4) * D); }

// w1 = exp(-i*pi*t/1024) via fast sincos; t small (<=510) so args <=1.6 rad.
__device__ __forceinline__ float2 tw(int t) {
    float s, c;
    __sincosf(-(float)t * (PI_F / 1024.0f), &s, &c);
    return make_float2(c, s);
}

template <int NS, int LOG2NS, int DIN, int DOUT>
__device__ __forceinline__ void stage(const float2* __restrict__ in,
                                      float2* __restrict__ out, int j) {
    float2 v[4];
#pragma unroll
    for (int r = 0; r < 4; r++) v[r] = in[pad<DIN>(j + r * 256)];
    {
        int m = j & (NS - 1);
        const int step = 2048 / (NS * 4);
        float2 w1 = tw(m * step);
        float2 w2 = cmul(w1, w1);
        float2 w3 = cmul(w2, w1);
        v[1] = cmul(v[1], w1);
        v[2] = cmul(v[2], w2);
        v[3] = cmul(v[3], w3);
    }
    bfly4(v);
    int idxD = ((j >> LOG2NS) << (LOG2NS + 2)) + (j & (NS - 1));
#pragma unroll
    for (int r = 0; r < 4; r++) out[pad<DOUT>(idxD + r * NS)] = v[r];
}

__global__ void __launch_bounds__(THREADS, 6)
fourier_ln_kernel(const float* __restrict__ x,
                  const float* __restrict__ gamma,
                  const float* __restrict__ beta,
                  float* __restrict__ out) {
    __shared__ __align__(16) float2 bufA[H + H / 16];          // pad D=1
    __shared__ __align__(16) float2 bufB[H + (H / 16) * 4];    // pad D=4
    __shared__ float red[18];

    const int j = threadIdx.x;
    const size_t row = blockIdx.x;
    const float2* xr = reinterpret_cast<const float2*>(x) + row * H;

    // stage Ns=1: global -> regs -> bufA (no twiddle)
    {
        float2 v[4];
#pragma unroll
        for (int r = 0; r < 4; r++) v[r] = xr[j + r * 256];
        bfly4(v);
#pragma unroll
        for (int r = 0; r < 4; r++) bufA[pad<1>(4 * j + r)] = v[r];
    }
    __syncthreads();
    stage<4, 2, 1, 4>(bufA, bufB, j);  __syncthreads();
    stage<16, 4, 4, 1>(bufB, bufA, j); __syncthreads();
    stage<64, 6, 1, 4>(bufA, bufB, j); __syncthreads();

    // final stage Ns=256: read bufB, keep Z[k=j+256r] in registers
    float2 z[4];
    {
#pragma unroll
        for (int r = 0; r < 4; r++) z[r] = bufB[pad<4>(j + r * 256)];
        float2 w1 = tw(2 * j);               // m=j, step=2
        float2 w2 = cmul(w1, w1);
        float2 w3 = cmul(w2, w1);
        z[1] = cmul(z[1], w1);
        z[2] = cmul(z[2], w2);
        z[3] = cmul(z[3], w3);
        bfly4(z);
    }

    // publish Z for conjugate-partner access (bufA free: all reads synced above)
#pragma unroll
    for (int r = 0; r < 4; r++) bufA[pad<1>(j + r * 256)] = z[r];
    __syncthreads();

    // real-FFT unpack in registers: ReX[k] = 0.5*((a+c) + wc*(b+d) + ws*(a-c))
    float re[4];
    float2 wj = tw(j);                       // exp(-i*pi*j/1024)
#pragma unroll
    for (int r = 0; r < 4; r++) {
        int k = j + r * 256;
        float2 zz = z[r];
        float2 zc = bufA[pad<1>((H - k) & (H - 1))];
        float2 w;
        if (r == 0)      w = wj;
        else if (r == 1) w = make_float2(RS2 * (wj.x + wj.y), RS2 * (wj.y - wj.x));
        else if (r == 2) w = make_float2(wj.y, -wj.x);
        else             w = make_float2(RS2 * (wj.y - wj.x), -RS2 * (wj.x + wj.y));
        re[r] = 0.5f * ((zz.x + zc.x) + fmaf(w.x, (zz.y + zc.y), w.y * (zz.x - zc.x)));
    }
    float re1024 = z[0].x - z[0].y;          // valid on thread 0 only (k=1024)

    // LayerNorm sums: every re[k] (k=1..1023) appears twice (mirror); k=0 and
    // k=1024 once.
    float s  = 2.0f * (re[0] + re[1] + re[2] + re[3]);
    float ss = 2.0f * fmaf(re[0], re[0], fmaf(re[1], re[1],
                    fmaf(re[2], re[2], re[3] * re[3])));
    if (j == 0) {
        s  += re1024 - re[0];
        ss += fmaf(re1024, re1024, -re[0] * re[0]);
    }
#pragma unroll
    for (int off = 16; off > 0; off >>= 1) {
        s  += __shfl_xor_sync(0xFFFFFFFFu, s, off);
        ss += __shfl_xor_sync(0xFFFFFFFFu, ss, off);
    }
    int lane = j & 31, wid = j >> 5;
    if (lane == 0) { red[wid] = s; red[8 + wid] = ss; }
    __syncthreads();
    if (j == 0) {
        float S = 0.f, SS = 0.f;
#pragma unroll
        for (int w = 0; w < 8; w++) { S += red[w]; SS += red[8 + w]; }
        float mu  = S * (1.0f / C);
        float var = SS * (1.0f / C) - mu * mu;
        red[16] = mu;
        red[17] = rsqrtf(var + 1e-5f);
    }
    __syncthreads();
    const float mu = red[16], rstd = red[17];

    // stores: out[k] and mirrored out[2048-k], straight from registers
    float* orow = out + row * C;
#pragma unroll
    for (int r = 0; r < 4; r++) {
        int k = j + r * 256;
        float v = (re[r] - mu) * rstd;
        orow[k] = fmaf(v, __ldg(&gamma[k]), __ldg(&beta[k]));
        if (k != 0) {
            int km = C - k;
            orow[km] = fmaf(v, __ldg(&gamma[km]), __ldg(&beta[km]));
        }
    }
    if (j == 0) {
        float v = (re1024 - mu) * rstd;
        orow[H] = fmaf(v, __ldg(&gamma[H]), __ldg(&beta[H]));
    }
}

extern "C" void kernel_launch(void* const* d_in, const int* in_sizes, int n_in,
                              void* d_out, int out_size) {
    const float* x     = (const float*)d_in[0];
    const float* gamma = (const float*)d_in[1];
    const float* beta  = (const float*)d_in[2];
    float* out = (float*)d_out;

    int rows = in_sizes[0] / C;   // B*N = 16384
    fourier_ln_kernel<<<rows, THREADS>>>(x, gamma, beta, out);
}

// round 4
// speedup vs baseline: 3.0025x; 1.1808x over previous
#include <cuda_runtime.h>
#include <cuda_bf16.h>

// y = Re(FFT_2048(x_row)); out = LayerNorm(y)*gamma + beta.  16384 rows, C=2048.
// Four-step FFT: 1024 = 32x32. One warp per row, 32 complex elems/thread.
// Register-resident FFT-32 (radix-2 DIF, constant twiddles), ONE padded smem
// transpose, conjugate unpack via warp shuffle, LN via warp reduce.

#define C 2048
#define H 1024
#define RPC 4            // rows (warps) per CTA
#define PITCH 33
#define PI_F 3.14159265358979323846f

__device__ __forceinline__ float2 cmul(float2 a, float2 b) {
    return make_float2(fmaf(a.x, b.x, -a.y * b.y), fmaf(a.x, b.y, a.y * b.x));
}
__device__ __forceinline__ float2 cadd(float2 a, float2 b) { return make_float2(a.x + b.x, a.y + b.y); }
__device__ __forceinline__ float2 csub(float2 a, float2 b) { return make_float2(a.x - b.x, a.y - b.y); }

__device__ __forceinline__ int br5(int x) {
    return ((x & 1) << 4) | ((x & 2) << 2) | (x & 4) | ((x & 8) >> 2) | ((x & 16) >> 4);
}

// W_32^e = exp(-2*pi*i*e/32), e in [0,16). Compile-time folded.
__device__ __forceinline__ float2 w32c(int e) {
    const float CO[16] = {1.f, 0.98078528f, 0.92387953f, 0.83146961f, 0.70710678f,
                          0.55557023f, 0.38268343f, 0.19509032f, 0.f, -0.19509032f,
                          -0.38268343f, -0.55557023f, -0.70710678f, -0.83146961f,
                          -0.92387953f, -0.98078528f};
    const float SI[16] = {0.f, 0.19509032f, 0.38268343f, 0.55557023f, 0.70710678f,
                          0.83146961f, 0.92387953f, 0.98078528f, 1.f, 0.98078528f,
                          0.92387953f, 0.83146961f, 0.70710678f, 0.55557023f,
                          0.38268343f, 0.19509032f};
    return make_float2(CO[e], -SI[e]);
}

template <int M>
__device__ __forceinline__ void fft32_stage(float2 v[32]) {
#pragma unroll
    for (int b = 0; b < 32; b += 2 * M)
#pragma unroll
        for (int i = 0; i < M; i++) {
            float2 u = v[b + i], t = v[b + i + M];
            v[b + i] = cadd(u, t);
            float2 d = csub(u, t);
            const int e = i * (16 / M);
            v[b + i + M] = (e == 0) ? d : cmul(d, w32c(e));
        }
}
// Radix-2 DIF: natural input order, output v[r] = X[br5(r)].
__device__ __forceinline__ void fft32(float2 v[32]) {
    fft32_stage<16>(v); fft32_stage<8>(v); fft32_stage<4>(v);
    fft32_stage<2>(v);  fft32_stage<1>(v);
}

__global__ void __launch_bounds__(128, 4)
fourier_ln_kernel(const float* __restrict__ x,
                  const float* __restrict__ gamma,
                  const float* __restrict__ beta,
                  float* __restrict__ out) {
    __shared__ __align__(16) float2 xch[RPC][32 * PITCH];

    const int lane = threadIdx.x & 31;
    const int warp = threadIdx.x >> 5;
    const size_t row = (size_t)blockIdx.x * RPC + warp;
    const float2* xr = reinterpret_cast<const float2*>(x) + row * H;

    // ---- step 1: load column a=lane (coalesced), FFT-32 over b ----
    float2 v[32];
#pragma unroll
    for (int b = 0; b < 32; b++) v[b] = xr[lane + 32 * b];
    fft32(v);                    // v[br5(c)] = G_a[c]

    // ---- step 2: twiddle G_a[c] *= W_1024^{a*c} (incremental powers) ----
    {
        float sb, cb;
        __sincosf(-(float)lane * (PI_F / 512.0f), &sb, &cb);   // base = W_1024^a
        float2 base = make_float2(cb, sb);
        float2 w = base;
#pragma unroll
        for (int c = 1; c < 32; c++) {
            v[br5(c)] = cmul(v[br5(c)], w);
            w = cmul(w, base);
        }
    }

    // ---- step 3: 32x32 transpose through padded smem (conflict-free) ----
    float2* sh = &xch[warp][0];
#pragma unroll
    for (int c = 0; c < 32; c++) sh[lane * PITCH + c] = v[br5(c)];
    __syncwarp();
    float2 g[32];
#pragma unroll
    for (int a = 0; a < 32; a++) g[a] = sh[a * PITCH + lane];

    // ---- step 4: FFT-32 over a.  g[br5(d)] = Z[lane + 32*d] ----
    fft32(g);

    const float re1024 = g[0].x - g[0].y;      // Z[0] -> ReX[1024] (lane 0)

    // ---- real-FFT unpack + LN partial sums.  k = lane + 32*d ----
    // partner of k: lane (32-lane)&31, reg br5(31-d)  (lane0: own br5((32-d)&31))
    float reA[16];
    float s = 0.f, ss = 0.f;
    {
        float su, cu;
        __sincosf(-(float)lane * (PI_F / 1024.0f), &su, &cu);  // e^{-i*pi*lane/1024}
        float2 wu = make_float2(cu, su);
        const float2 ustep = make_float2(0.99518472667f, -0.09801714033f); // e^{-i*pi/32}
        const int psrc = (32 - lane) & 31;
#pragma unroll
        for (int d = 0; d < 32; d++) {
            float2 z = g[br5(d)];
            float px = __shfl_sync(0xFFFFFFFFu, g[br5(31 - d)].x, psrc);
            float py = __shfl_sync(0xFFFFFFFFu, g[br5(31 - d)].y, psrc);
            if (lane == 0) {
                float2 o = g[br5((32 - d) & 31)];
                px = o.x; py = o.y;
            }
            float red = 0.5f * ((z.x + px) + fmaf(wu.x, z.y + py, wu.y * (z.x - px)));
            if (d < 16) reA[d] = red;
            else        g[br5(d)].x = red;     // slots br5(16..31): shfl sources done
            s  += 2.0f * red;
            ss = fmaf(2.0f * red, red, ss);
            wu = cmul(wu, ustep);
        }
    }
    if (lane == 0) {               // k=0 and k=1024 each count once, not twice
        s  += re1024 - reA[0];
        ss += fmaf(re1024, re1024, -reA[0] * reA[0]);
    }
#pragma unroll
    for (int o = 16; o > 0; o >>= 1) {
        s  += __shfl_xor_sync(0xFFFFFFFFu, s, o);
        ss += __shfl_xor_sync(0xFFFFFFFFu, ss, o);
    }
    const float mu = s * (1.0f / C);
    const float rstd = rsqrtf(ss * (1.0f / C) - mu * mu + 1e-5f);

    // ---- normalize + affine + mirrored stores ----
    float* orow = out + row * C;
#pragma unroll
    for (int d = 0; d < 32; d++) {
        float red = (d < 16) ? reA[d] : g[br5(d)].x;
        int k = lane + 32 * d;
        float vv = (red - mu) * rstd;
        orow[k] = fmaf(vv, __ldg(&gamma[k]), __ldg(&beta[k]));
        if (k != 0) {
            int km = C - k;
            orow[km] = fmaf(vv, __ldg(&gamma[km]), __ldg(&beta[km]));
        }
    }
    if (lane == 0) {
        float vv = (re1024 - mu) * rstd;
        orow[H] = fmaf(vv, __ldg(&gamma[H]), __ldg(&beta[H]));
    }
}

extern "C" void kernel_launch(void* const* d_in, const int* in_sizes, int n_in,
                              void* d_out, int out_size) {
    const float* x     = (const float*)d_in[0];
    const float* gamma = (const float*)d_in[1];
    const float* beta  = (const float*)d_in[2];
    float* out = (float*)d_out;

    int rows = in_sizes[0] / C;            // 16384
    fourier_ln_kernel<<<rows / RPC, 32 * RPC>>>(x, gamma, beta, out);
}

// round 6
// speedup vs baseline: 3.5527x; 1.1833x over previous
#include <cuda_runtime.h>
#include <cuda_bf16.h>

// y = Re(FFT_2048(x_row)); out = LayerNorm(y)*gamma + beta.  16384 rows, C=2048.
// Four-step FFT: 1024 = 32x32, one warp/row, 32 complex elems/thread.
// Register FFT-32 (radix-2 DIF, const twiddles), one padded smem transpose,
// conjugate unpack via linear smem (conflict-free), LN warp reduce.
// Twiddle chains broken to depth<=8 (4 parallel chains in unpack; squaring
// ladder in step 2).

#define C 2048
#define H 1024
#define RPC 4
#define PITCH 33
#define PI_F 3.14159265358979323846f
#define RS2 0.70710678118654752f

__device__ __forceinline__ float2 cmul(float2 a, float2 b) {
    return make_float2(fmaf(a.x, b.x, -a.y * b.y), fmaf(a.x, b.y, a.y * b.x));
}
__device__ __forceinline__ float2 csq(float2 a) {
    return make_float2(fmaf(a.x, a.x, -a.y * a.y), 2.0f * a.x * a.y);
}
__device__ __forceinline__ float2 cadd(float2 a, float2 b) { return make_float2(a.x + b.x, a.y + b.y); }
__device__ __forceinline__ float2 csub(float2 a, float2 b) { return make_float2(a.x - b.x, a.y - b.y); }

__device__ __forceinline__ int br5(int x) {
    return ((x & 1) << 4) | ((x & 2) << 2) | (x & 4) | ((x & 8) >> 2) | ((x & 16) >> 4);
}

__device__ __forceinline__ float2 w32c(int e) {
    const float CO[16] = {1.f, 0.98078528f, 0.92387953f, 0.83146961f, 0.70710678f,
                          0.55557023f, 0.38268343f, 0.19509032f, 0.f, -0.19509032f,
                          -0.38268343f, -0.55557023f, -0.70710678f, -0.83146961f,
                          -0.92387953f, -0.98078528f};
    const float SI[16] = {0.f, 0.19509032f, 0.38268343f, 0.55557023f, 0.70710678f,
                          0.83146961f, 0.92387953f, 0.98078528f, 1.f, 0.98078528f,
                          0.92387953f, 0.83146961f, 0.70710678f, 0.55557023f,
                          0.38268343f, 0.19509032f};
    return make_float2(CO[e], -SI[e]);
}

template <int M>
__device__ __forceinline__ void fft32_stage(float2 v[32]) {
#pragma unroll
    for (int b = 0; b < 32; b += 2 * M)
#pragma unroll
        for (int i = 0; i < M; i++) {
            float2 u = v[b + i], t = v[b + i + M];
            v[b + i] = cadd(u, t);
            float2 d = csub(u, t);
            const int e = i * (16 / M);
            if (e == 0)      v[b + i + M] = d;
            else if (e == 8) v[b + i + M] = make_float2(d.y, -d.x);  // *(-i)
            else             v[b + i + M] = cmul(d, w32c(e));
        }
}
__device__ __forceinline__ void fft32(float2 v[32]) {
    fft32_stage<16>(v); fft32_stage<8>(v); fft32_stage<4>(v);
    fft32_stage<2>(v);  fft32_stage<1>(v);
}

__global__ void __launch_bounds__(128, 5)
fourier_ln_kernel(const float* __restrict__ x,
                  const float* __restrict__ gamma,
                  const float* __restrict__ beta,
                  float* __restrict__ out) {
    __shared__ __align__(16) float2 xch[RPC][32 * PITCH];

    const int lane = threadIdx.x & 31;
    const int warp = threadIdx.x >> 5;
    const size_t row = (size_t)blockIdx.x * RPC + warp;
    const float2* xr = reinterpret_cast<const float2*>(x) + row * H;

    // step 1: coalesced load, FFT-32 over b
    float2 g[32];
#pragma unroll
    for (int b = 0; b < 32; b++) g[b] = xr[lane + 32 * b];
    fft32(g);                    // g[br5(c)] = G_a[c]

    // step 2: G_a[c] *= W_1024^{a*c}; squaring ladder (depth ~5)
    {
        float sb, cb;
        __sincosf(-(float)lane * (PI_F / 512.0f), &sb, &cb);
        float2 p1 = make_float2(cb, sb);
        float2 p2 = csq(p1), p3 = cmul(p1, p2), p4 = csq(p2);
        float2 p5 = cmul(p4, p1), p6 = csq(p3), p7 = cmul(p4, p3);
        float2 w8 = csq(p4), w16 = csq(w8), w24 = cmul(w16, w8);
        g[br5(8)]  = cmul(g[br5(8)],  w8);
        g[br5(16)] = cmul(g[br5(16)], w16);
        g[br5(24)] = cmul(g[br5(24)], w24);
        float2 pc[7] = {p1, p2, p3, p4, p5, p6, p7};
#pragma unroll
        for (int c = 1; c < 8; c++) {
            float2 w = pc[c - 1];
            g[br5(c)]      = cmul(g[br5(c)], w);
            g[br5(c + 8)]  = cmul(g[br5(c + 8)],  cmul(w, w8));
            g[br5(c + 16)] = cmul(g[br5(c + 16)], cmul(w, w16));
            g[br5(c + 24)] = cmul(g[br5(c + 24)], cmul(w, w24));
        }
    }

    // step 3: 32x32 transpose through padded smem
    float2* sh = &xch[warp][0];
#pragma unroll
    for (int c = 0; c < 32; c++) sh[lane * PITCH + c] = g[br5(c)];
    __syncwarp();
#pragma unroll
    for (int a = 0; a < 32; a++) g[a] = sh[a * PITCH + lane];
    __syncwarp();

    // step 4: FFT-32 over a.  g[br5(d)] = Z[lane + 32*d]
    fft32(g);
    const float re1024 = g[0].x - g[0].y;      // lane 0: ReX[1024]

    // publish Z linearly for conjugate-partner reads (conflict-free)
#pragma unroll
    for (int d = 0; d < 32; d++) sh[lane + 32 * d] = g[br5(d)];
    __syncwarp();

    // unpack ReX[k] + LN partials; one depth-8 chain drives 4 groups
    float s = 0.f, ss = 0.f;
    {
        float su, cu;
        __sincosf(-(float)lane * (PI_F / 1024.0f), &su, &cu);
        float2 wu = make_float2(cu, su);                        // e^{-i pi k/1024}, k=lane
        const float2 ustep = make_float2(0.99518472667f, -0.09801714033f); // e^{-i pi/32}
        const float2 c8  = make_float2(RS2, -RS2);              // e^{-i pi/4}
        const float2 c24 = make_float2(-RS2, -RS2);             // e^{-i 3pi/4}
#pragma unroll
        for (int dd = 0; dd < 8; dd++) {
#pragma unroll
            for (int q = 0; q < 4; q++) {
                const int d = q * 8 + dd;
                float2 w;
                if (q == 0)      w = wu;
                else if (q == 1) w = cmul(wu, c8);
                else if (q == 2) w = make_float2(wu.y, -wu.x);  // wu * (-i)
                else             w = cmul(wu, c24);
                int k = lane + 32 * d;
                float2 z = g[br5(d)];
                float2 p = sh[(H - k) & (H - 1)];
                float red = 0.5f * ((z.x + p.x) +
                            fmaf(w.x, z.y + p.y, w.y * (z.x - p.x)));
                g[br5(d)].x = red;
                s  += 2.0f * red;
                ss = fmaf(2.0f * red, red, ss);
            }
            if (dd < 7) wu = cmul(wu, ustep);
        }
    }
    if (lane == 0) {
        float re0 = g[br5(0)].x;
        s  += re1024 - re0;
        ss += fmaf(re1024, re1024, -re0 * re0);
    }
#pragma unroll
    for (int o = 16; o > 0; o >>= 1) {
        s  += __shfl_xor_sync(0xFFFFFFFFu, s, o);
        ss += __shfl_xor_sync(0xFFFFFFFFu, ss, o);
    }
    const float mu = s * (1.0f / C);
    const float rstd = rsqrtf(ss * (1.0f / C) - mu * mu + 1e-5f);

    // normalize + affine + mirrored stores
    float* orow = out + row * C;
#pragma unroll
    for (int d = 0; d < 32; d++) {
        int k = lane + 32 * d;
        float vv = (g[br5(d)].x - mu) * rstd;
        orow[k] = fmaf(vv, __ldg(&gamma[k]), __ldg(&beta[k]));
        if (k != 0) {
            int km = C - k;
            orow[km] = fmaf(vv, __ldg(&gamma[km]), __ldg(&beta[km]));
        }
    }
    if (lane == 0) {
        float vv = (re1024 - mu) * rstd;
        orow[H] = fmaf(vv, __ldg(&gamma[H]), __ldg(&beta[H]));
    }
}

extern "C" void kernel_launch(void* const* d_in, const int* in_sizes, int n_in,
                              void* d_out, int out_size) {
    const float* x     = (const float*)d_in[0];
    const float* gamma = (const float*)d_in[1];
    const float* beta  = (const float*)d_in[2];
    float* out = (float*)d_out;
    int rows = in_sizes[0] / C;            // 16384
    fourier_ln_kernel<<<rows / RPC, 32 * RPC>>>(x, gamma, beta, out);
}